// round 5
// baseline (speedup 1.0000x reference)
#include <cuda_runtime.h>
#include <cstddef>

#define NNODES 10000
#define NEDGES 320000
#define FDIM   128

// ---------------- device scratch (allocation-free rule: __device__ globals) ---
__device__ float g_B1[NNODES * FDIM];   // h1 / a1out / s1out
__device__ float g_B2[NNODES * FDIM];   // h2
__device__ float g_AGG[NNODES * FDIM];  // aggregation buffer (pre-scaled by 1/deg)
__device__ float g_inv[NNODES];
__device__ int   g_deg[NNODES];
__device__ int   g_cur[NNODES];
__device__ int   g_ptr[NNODES + 1];
__device__ int   g_csrc[NEDGES];

// ---------------- CSR construction -------------------------------------------
__global__ void zero_kernel() {
    int i = blockIdx.x * blockDim.x + threadIdx.x;
    if (i < NNODES) { g_deg[i] = 0; g_cur[i] = 0; }
}

__global__ void count_kernel(const int* __restrict__ dst) {
    int e = blockIdx.x * blockDim.x + threadIdx.x;
    if (e < NEDGES) atomicAdd(&g_deg[dst[e]], 1);
}

// single-block inclusive scan (Hillis-Steele, 1024 threads, chunked with carry)
__global__ void scan_kernel() {
    __shared__ int sh[1024];
    int carry = 0;
    for (int base = 0; base < NNODES; base += 1024) {
        int i = base + threadIdx.x;
        int v = (i < NNODES) ? g_deg[i] : 0;
        sh[threadIdx.x] = v;
        __syncthreads();
        for (int off = 1; off < 1024; off <<= 1) {
            int t = (threadIdx.x >= off) ? sh[threadIdx.x - off] : 0;
            __syncthreads();
            sh[threadIdx.x] += t;
            __syncthreads();
        }
        if (i < NNODES) {
            g_ptr[i] = carry + sh[threadIdx.x] - v;           // exclusive
            g_inv[i] = 1.0f / fmaxf((float)v, 1.0f);
        }
        carry += sh[1023];
        __syncthreads();
    }
    if (threadIdx.x == 0) g_ptr[NNODES] = carry;
}

__global__ void fill_kernel(const int* __restrict__ src, const int* __restrict__ dst) {
    int e = blockIdx.x * blockDim.x + threadIdx.x;
    if (e < NEDGES) {
        int d = dst[e];
        int pos = g_ptr[d] + atomicAdd(&g_cur[d], 1);
        g_csrc[pos] = src[e];
    }
}

// ---------------- mean aggregation: one block (128 thr) per node --------------
__global__ void agg_kernel(const float* __restrict__ X) {
    int node = blockIdx.x;
    int t = threadIdx.x;
    int beg = g_ptr[node], end = g_ptr[node + 1];
    float s0 = 0.f, s1 = 0.f, s2 = 0.f, s3 = 0.f;
    int e = beg;
    for (; e + 4 <= end; e += 4) {
        int i0 = g_csrc[e], i1 = g_csrc[e + 1], i2 = g_csrc[e + 2], i3 = g_csrc[e + 3];
        s0 += X[i0 * FDIM + t];
        s1 += X[i1 * FDIM + t];
        s2 += X[i2 * FDIM + t];
        s3 += X[i3 * FDIM + t];
    }
    for (; e < end; e++) s0 += X[g_csrc[e] * FDIM + t];
    g_AGG[node * FDIM + t] = (s0 + s1 + s2 + s3) * g_inv[node];
}

// ---------------- fused SAGE layer: Y = relu(AGG@Wl + X@Wr + b), dout=128 -----
// BM=64 rows x BN=128 cols, 128 threads, 8x8 microtile, BK=8, 2 K-phases.
__global__ void layer_kernel(const float* __restrict__ A0,  // AGG [N,128] (scaled)
                             const float* __restrict__ A1,  // root feats [N,128]
                             const float* __restrict__ W0,  // Wl [128,128]
                             const float* __restrict__ W1,  // Wr [128,128]
                             const float* __restrict__ bias,// [128]
                             float* __restrict__ Y) {       // [N,128]
    __shared__ float As[8][64];
    __shared__ float Bs[8][128];
    int tid = threadIdx.x;
    int r0 = blockIdx.x * 64;

    float acc[8][8];
#pragma unroll
    for (int i = 0; i < 8; i++)
#pragma unroll
        for (int j = 0; j < 8; j++) acc[i][j] = 0.f;

    int lrow = tid >> 1;            // 0..63
    int lc   = (tid & 1) * 4;       // 0 or 4
    int rowb = (tid >> 4) * 8;      // 0..56
    int colb = (tid & 15) * 8;      // 0..120

    for (int phase = 0; phase < 2; phase++) {
        const float* A = phase ? A1 : A0;
        const float* W = phase ? W1 : W0;
        for (int k0 = 0; k0 < 128; k0 += 8) {
            // A tile: 64 rows x 8 k, transposed into As[k][row]
            float4 av = make_float4(0.f, 0.f, 0.f, 0.f);
            int grow = r0 + lrow;
            if (grow < NNODES) av = *(const float4*)&A[grow * FDIM + k0 + lc];
            As[lc + 0][lrow] = av.x;
            As[lc + 1][lrow] = av.y;
            As[lc + 2][lrow] = av.z;
            As[lc + 3][lrow] = av.w;
            // B tile: 8 k x 128 cols (row-major, coalesced)
            {
                int idx = tid;
                int kk = idx >> 5, j4 = (idx & 31) * 4;
                *(float4*)&Bs[kk][j4] = *(const float4*)&W[(k0 + kk) * 128 + j4];
                idx = tid + 128;
                kk = idx >> 5; j4 = (idx & 31) * 4;
                *(float4*)&Bs[kk][j4] = *(const float4*)&W[(k0 + kk) * 128 + j4];
            }
            __syncthreads();
#pragma unroll
            for (int k = 0; k < 8; k++) {
                float a[8], b[8];
                *(float4*)&a[0] = *(const float4*)&As[k][rowb];
                *(float4*)&a[4] = *(const float4*)&As[k][rowb + 4];
                *(float4*)&b[0] = *(const float4*)&Bs[k][colb];
                *(float4*)&b[4] = *(const float4*)&Bs[k][colb + 4];
#pragma unroll
                for (int ii = 0; ii < 8; ii++)
#pragma unroll
                    for (int jj = 0; jj < 8; jj++) acc[ii][jj] += a[ii] * b[jj];
            }
            __syncthreads();
        }
    }
#pragma unroll
    for (int ii = 0; ii < 8; ii++) {
        int grow = r0 + rowb + ii;
        if (grow < NNODES) {
#pragma unroll
            for (int jj = 0; jj < 8; jj += 4) {
                float4 o;
                o.x = fmaxf(acc[ii][jj + 0] + bias[colb + jj + 0], 0.f);
                o.y = fmaxf(acc[ii][jj + 1] + bias[colb + jj + 1], 0.f);
                o.z = fmaxf(acc[ii][jj + 2] + bias[colb + jj + 2], 0.f);
                o.w = fmaxf(acc[ii][jj + 3] + bias[colb + jj + 3], 0.f);
                *(float4*)&Y[(size_t)grow * 128 + colb + jj] = o;
            }
        }
    }
}

// ---------------- final layer, computed transposed ----------------------------
// OUT[i*N + j] = relu( sum_k Wl[k,i]*AGG[j,k] + sum_k Wr[k,i]*S1[j,k] + b[i] )
// BM=128 (out-dim i) x BN=128 (node j), 256 threads, 8x8 microtile, BK=8.
__global__ void final_kernel(const float* __restrict__ AGG,  // [N,128] (scaled)
                             const float* __restrict__ S1,   // [N,128]
                             const float* __restrict__ Wl,   // [128, N]
                             const float* __restrict__ Wr,   // [128, N]
                             const float* __restrict__ bias, // [N]
                             float* __restrict__ OUT) {      // [N, N]
    __shared__ float As[8][128];  // weights: As[k][i]
    __shared__ float Bs[8][128];  // feats:   Bs[k][j]
    int tid = threadIdx.x;
    int ib = blockIdx.y * 128;
    int jb = blockIdx.x * 128;

    float acc[8][8];
#pragma unroll
    for (int i = 0; i < 8; i++)
#pragma unroll
        for (int j = 0; j < 8; j++) acc[i][j] = 0.f;

    int akk = tid >> 5;             // 0..7
    int ai4 = (tid & 31) * 4;       // 0..124
    int bj  = tid >> 1;             // 0..127
    int bc  = (tid & 1) * 4;        // 0 or 4
    int rowb = (tid >> 4) * 8;      // i tile offset 0..120
    int colb = (tid & 15) * 8;      // j tile offset 0..120

    for (int phase = 0; phase < 2; phase++) {
        const float* W  = phase ? Wr : Wl;
        const float* Ft = phase ? S1 : AGG;
        for (int k0 = 0; k0 < 128; k0 += 8) {
            // weight tile: W[k, ib+i] row-major along i -> coalesced, no transpose
            float4 av = make_float4(0.f, 0.f, 0.f, 0.f);
            if (ib + ai4 < NNODES)
                av = *(const float4*)&W[(size_t)(k0 + akk) * NNODES + ib + ai4];
            *(float4*)&As[akk][ai4] = av;
            // feature tile: Ft[jb+j, k], transposed into Bs[k][j]
            float4 bv = make_float4(0.f, 0.f, 0.f, 0.f);
            if (jb + bj < NNODES)
                bv = *(const float4*)&Ft[(size_t)(jb + bj) * FDIM + k0 + bc];
            Bs[bc + 0][bj] = bv.x;
            Bs[bc + 1][bj] = bv.y;
            Bs[bc + 2][bj] = bv.z;
            Bs[bc + 3][bj] = bv.w;
            __syncthreads();
#pragma unroll
            for (int k = 0; k < 8; k++) {
                float a[8], b[8];
                *(float4*)&a[0] = *(const float4*)&As[k][rowb];
                *(float4*)&a[4] = *(const float4*)&As[k][rowb + 4];
                *(float4*)&b[0] = *(const float4*)&Bs[k][colb];
                *(float4*)&b[4] = *(const float4*)&Bs[k][colb + 4];
#pragma unroll
                for (int ii = 0; ii < 8; ii++)
#pragma unroll
                    for (int jj = 0; jj < 8; jj++) acc[ii][jj] += a[ii] * b[jj];
            }
            __syncthreads();
        }
    }
    bool jvalid = (jb + colb) < NNODES;  // N%8==0 -> all-or-nothing per thread
    if (jvalid) {
#pragma unroll
        for (int ii = 0; ii < 8; ii++) {
            int gi = ib + rowb + ii;
            if (gi < NNODES) {
                float bval = bias[gi];
                float4 o0, o1;
                o0.x = fmaxf(acc[ii][0] + bval, 0.f);
                o0.y = fmaxf(acc[ii][1] + bval, 0.f);
                o0.z = fmaxf(acc[ii][2] + bval, 0.f);
                o0.w = fmaxf(acc[ii][3] + bval, 0.f);
                o1.x = fmaxf(acc[ii][4] + bval, 0.f);
                o1.y = fmaxf(acc[ii][5] + bval, 0.f);
                o1.z = fmaxf(acc[ii][6] + bval, 0.f);
                o1.w = fmaxf(acc[ii][7] + bval, 0.f);
                size_t base = (size_t)gi * NNODES + jb + colb;
                *(float4*)&OUT[base]     = o0;
                *(float4*)&OUT[base + 4] = o1;
            }
        }
    }
}

// ---------------- launch ------------------------------------------------------
extern "C" void kernel_launch(void* const* d_in, const int* in_sizes, int n_in,
                              void* d_out, int out_size) {
    const float* x   = (const float*)d_in[0];
    const int*   ei  = (const int*)d_in[1];
    const int*   src = ei;
    const int*   dst = ei + NEDGES;
    const float *Wl_e1 = (const float*)d_in[2],  *bl_e1 = (const float*)d_in[3],  *Wr_e1 = (const float*)d_in[4];
    const float *Wl_e2 = (const float*)d_in[5],  *bl_e2 = (const float*)d_in[6],  *Wr_e2 = (const float*)d_in[7];
    const float *Wl_a1 = (const float*)d_in[8],  *bl_a1 = (const float*)d_in[9],  *Wr_a1 = (const float*)d_in[10];
    const float *Wl_a2 = (const float*)d_in[11], *bl_a2 = (const float*)d_in[12], *Wr_a2 = (const float*)d_in[13];
    const float *Wl_s1 = (const float*)d_in[14], *bl_s1 = (const float*)d_in[15], *Wr_s1 = (const float*)d_in[16];
    const float *Wl_s2 = (const float*)d_in[17], *bl_s2 = (const float*)d_in[18], *Wr_s2 = (const float*)d_in[19];

    float* out    = (float*)d_out;
    float* xh_out = out + (size_t)NNODES * NNODES;

    float *pB1, *pB2, *pAGG;
    cudaGetSymbolAddress((void**)&pB1,  g_B1);
    cudaGetSymbolAddress((void**)&pB2,  g_B2);
    cudaGetSymbolAddress((void**)&pAGG, g_AGG);

    // CSR build
    zero_kernel<<<(NNODES + 255) / 256, 256>>>();
    count_kernel<<<(NEDGES + 255) / 256, 256>>>(dst);
    scan_kernel<<<1, 1024>>>();
    fill_kernel<<<(NEDGES + 255) / 256, 256>>>(src, dst);

    const int LG = (NNODES + 63) / 64;   // 157 blocks for small layers
    dim3 fg((NNODES + 127) / 128, (NNODES + 127) / 128);  // 79x79

    // encoder
    agg_kernel<<<NNODES, 128>>>(x);
    layer_kernel<<<LG, 128>>>(pAGG, x, Wl_e1, Wr_e1, bl_e1, pB1);      // h1
    agg_kernel<<<NNODES, 128>>>(pB1);
    layer_kernel<<<LG, 128>>>(pAGG, pB1, Wl_e2, Wr_e2, bl_e2, pB2);    // h2
    // attribute decoder
    agg_kernel<<<NNODES, 128>>>(pB2);
    layer_kernel<<<LG, 128>>>(pAGG, pB2, Wl_a1, Wr_a1, bl_a1, pB1);    // a1
    agg_kernel<<<NNODES, 128>>>(pB1);
    layer_kernel<<<LG, 128>>>(pAGG, pB1, Wl_a2, Wr_a2, bl_a2, xh_out); // xh -> d_out tail
    // structure decoder
    agg_kernel<<<NNODES, 128>>>(pB2);
    layer_kernel<<<LG, 128>>>(pAGG, pB2, Wl_s1, Wr_s1, bl_s1, pB1);    // s1
    agg_kernel<<<NNODES, 128>>>(pB1);
    final_kernel<<<fg, 256>>>(pAGG, pB1, Wl_s2, Wr_s2, bl_s2, out);    // s (transposed) -> d_out head
}

// round 8
// speedup vs baseline: 1.9119x; 1.9119x over previous
#include <cuda_runtime.h>
#include <cstdint>
#include <cstddef>

#define NNODES 10000
#define NEDGES 320000
#define FDIM   128

// ---------------- device scratch (allocation-free rule: __device__ globals) ---
__device__ float g_B1[NNODES * FDIM];   // h1 / a1out / s1out
__device__ float g_B2[NNODES * FDIM];   // h2
__device__ float g_AGG[NNODES * FDIM];  // aggregation buffer (pre-scaled by 1/deg)
__device__ float g_inv[NNODES];
__device__ int   g_deg[NNODES];
__device__ int   g_cur[NNODES];
__device__ int   g_ptr[NNODES + 1];
__device__ int   g_csrc[NEDGES];

// ---------------- CSR construction -------------------------------------------
__global__ void zero_kernel() {
    int i = blockIdx.x * blockDim.x + threadIdx.x;
    if (i < NNODES) { g_deg[i] = 0; g_cur[i] = 0; }
}

__global__ void count_kernel(const int* __restrict__ dst) {
    int e = blockIdx.x * blockDim.x + threadIdx.x;
    if (e < NEDGES) atomicAdd(&g_deg[dst[e]], 1);
}

__global__ void scan_kernel() {
    __shared__ int sh[1024];
    int carry = 0;
    for (int base = 0; base < NNODES; base += 1024) {
        int i = base + threadIdx.x;
        int v = (i < NNODES) ? g_deg[i] : 0;
        sh[threadIdx.x] = v;
        __syncthreads();
        for (int off = 1; off < 1024; off <<= 1) {
            int t = (threadIdx.x >= off) ? sh[threadIdx.x - off] : 0;
            __syncthreads();
            sh[threadIdx.x] += t;
            __syncthreads();
        }
        if (i < NNODES) {
            g_ptr[i] = carry + sh[threadIdx.x] - v;           // exclusive
            g_inv[i] = 1.0f / fmaxf((float)v, 1.0f);
        }
        carry += sh[1023];
        __syncthreads();
    }
    if (threadIdx.x == 0) g_ptr[NNODES] = carry;
}

__global__ void fill_kernel(const int* __restrict__ src, const int* __restrict__ dst) {
    int e = blockIdx.x * blockDim.x + threadIdx.x;
    if (e < NEDGES) {
        int d = dst[e];
        int pos = g_ptr[d] + atomicAdd(&g_cur[d], 1);
        g_csrc[pos] = src[e];
    }
}

// ---------------- mean aggregation: one block (128 thr) per node --------------
__global__ void agg_kernel(const float* __restrict__ X) {
    int node = blockIdx.x;
    int t = threadIdx.x;
    int beg = g_ptr[node], end = g_ptr[node + 1];
    float s0 = 0.f, s1 = 0.f, s2 = 0.f, s3 = 0.f;
    int e = beg;
    for (; e + 4 <= end; e += 4) {
        int i0 = g_csrc[e], i1 = g_csrc[e + 1], i2 = g_csrc[e + 2], i3 = g_csrc[e + 3];
        s0 += X[i0 * FDIM + t];
        s1 += X[i1 * FDIM + t];
        s2 += X[i2 * FDIM + t];
        s3 += X[i3 * FDIM + t];
    }
    for (; e < end; e++) s0 += X[g_csrc[e] * FDIM + t];
    g_AGG[node * FDIM + t] = (s0 + s1 + s2 + s3) * g_inv[node];
}

// ---------------- fused SAGE layer: Y = relu(AGG@Wl + X@Wr + b), dout=128 -----
__global__ void layer_kernel(const float* __restrict__ A0,
                             const float* __restrict__ A1,
                             const float* __restrict__ W0,
                             const float* __restrict__ W1,
                             const float* __restrict__ bias,
                             float* __restrict__ Y) {
    __shared__ float As[8][64];
    __shared__ float Bs[8][128];
    int tid = threadIdx.x;
    int r0 = blockIdx.x * 64;

    float acc[8][8];
#pragma unroll
    for (int i = 0; i < 8; i++)
#pragma unroll
        for (int j = 0; j < 8; j++) acc[i][j] = 0.f;

    int lrow = tid >> 1;
    int lc   = (tid & 1) * 4;
    int rowb = (tid >> 4) * 8;
    int colb = (tid & 15) * 8;

    for (int phase = 0; phase < 2; phase++) {
        const float* A = phase ? A1 : A0;
        const float* W = phase ? W1 : W0;
        for (int k0 = 0; k0 < 128; k0 += 8) {
            float4 av = make_float4(0.f, 0.f, 0.f, 0.f);
            int grow = r0 + lrow;
            if (grow < NNODES) av = *(const float4*)&A[grow * FDIM + k0 + lc];
            As[lc + 0][lrow] = av.x;
            As[lc + 1][lrow] = av.y;
            As[lc + 2][lrow] = av.z;
            As[lc + 3][lrow] = av.w;
            {
                int idx = tid;
                int kk = idx >> 5, j4 = (idx & 31) * 4;
                *(float4*)&Bs[kk][j4] = *(const float4*)&W[(k0 + kk) * 128 + j4];
                idx = tid + 128;
                kk = idx >> 5; j4 = (idx & 31) * 4;
                *(float4*)&Bs[kk][j4] = *(const float4*)&W[(k0 + kk) * 128 + j4];
            }
            __syncthreads();
#pragma unroll
            for (int k = 0; k < 8; k++) {
                float a[8], b[8];
                *(float4*)&a[0] = *(const float4*)&As[k][rowb];
                *(float4*)&a[4] = *(const float4*)&As[k][rowb + 4];
                *(float4*)&b[0] = *(const float4*)&Bs[k][colb];
                *(float4*)&b[4] = *(const float4*)&Bs[k][colb + 4];
#pragma unroll
                for (int ii = 0; ii < 8; ii++)
#pragma unroll
                    for (int jj = 0; jj < 8; jj++) acc[ii][jj] += a[ii] * b[jj];
            }
            __syncthreads();
        }
    }
#pragma unroll
    for (int ii = 0; ii < 8; ii++) {
        int grow = r0 + rowb + ii;
        if (grow < NNODES) {
#pragma unroll
            for (int jj = 0; jj < 8; jj += 4) {
                float4 o;
                o.x = fmaxf(acc[ii][jj + 0] + bias[colb + jj + 0], 0.f);
                o.y = fmaxf(acc[ii][jj + 1] + bias[colb + jj + 1], 0.f);
                o.z = fmaxf(acc[ii][jj + 2] + bias[colb + jj + 2], 0.f);
                o.w = fmaxf(acc[ii][jj + 3] + bias[colb + jj + 3], 0.f);
                *(float4*)&Y[(size_t)grow * 128 + colb + jj] = o;
            }
        }
    }
}

// ================== tf32 mma.sync final GEMM (sm_80+ path) ===================
// OUT[i,j] = relu( sum_k Wl[k,i]*AGG[j,k] + sum_k Wr[k,i]*S1[j,k] + b[i] )
// CTA tile 128(i) x 128(j), K=256. 8 warps (2x4), warp tile 64x32.
// mma.sync.m16n8k8 tf32, fp32 accum in registers.
//
// SMEM fragment-shuffled layout (tf32 pre-converted during staging):
//   A frag slot (kt,mt,lane,r):  sA[((kt*8+mt)*32 + (lane^(kt<<3)))*4 + r]
//       element: m = mt*16 + (lane>>2) + (r&1)*8 ; k = kt*8 + (lane&3) + (r>>1)*4
//   B frag slot (kt,nt,lane,r):  sB[((kt*16+nt)*32 + (lane^(kt<<3)))*2 + r]
//       element: n = nt*8 + (lane>>2) ; k = kt*8 + (lane&3) + r*4
// -> each A fragment = one LDS.128, each B fragment = one LDS.64, conflict-free.

__device__ __forceinline__ uint32_t f2tf32(float v) {
    uint32_t t;
    asm("cvt.rna.tf32.f32 %0, %1;" : "=r"(t) : "f"(v));
    return t;
}

__device__ __forceinline__ void mma_tf32(float* c, const uint32_t* a, const uint32_t* b) {
    asm volatile(
        "mma.sync.aligned.m16n8k8.row.col.f32.tf32.tf32.f32 "
        "{%0,%1,%2,%3}, {%4,%5,%6,%7}, {%8,%9}, {%0,%1,%2,%3};\n"
        : "+f"(c[0]), "+f"(c[1]), "+f"(c[2]), "+f"(c[3])
        : "r"(a[0]), "r"(a[1]), "r"(a[2]), "r"(a[3]),
          "r"(b[0]), "r"(b[1]));
}

__global__ void __launch_bounds__(256, 2)
final_tc_kernel(const float* __restrict__ AGG,   // [N,128] (pre-scaled)
                const float* __restrict__ S1,    // [N,128]
                const float* __restrict__ Wl,    // [128, NNODES]
                const float* __restrict__ Wr,    // [128, NNODES]
                const float* __restrict__ bias,  // [NNODES]
                float* __restrict__ OUT) {       // [NNODES, NNODES]
    __shared__ __align__(16) uint32_t sA[4096];  // 16KB
    __shared__ __align__(16) uint32_t sB[4096];  // 16KB

    const int tid  = threadIdx.x;
    const int lane = tid & 31;
    const int warp = tid >> 5;
    const int wm   = warp >> 2;     // 0..1
    const int wn   = warp & 3;      // 0..3
    const int ib   = blockIdx.y * 128;
    const int jb   = blockIdx.x * 128;

    float acc[4][4][4];
#pragma unroll
    for (int mi = 0; mi < 4; mi++)
#pragma unroll
        for (int ni = 0; ni < 4; ni++)
#pragma unroll
            for (int r = 0; r < 4; r++) acc[mi][ni][r] = 0.f;

    for (int chunk = 0; chunk < 8; chunk++) {
        const int phase = chunk >> 2;
        const int kc = (chunk & 3) * 32;
        const float* __restrict__ W = phase ? Wr : Wl;    // [128, NNODES]
        const float* __restrict__ F = phase ? S1 : AGG;   // [NNODES, 128]

        __syncthreads();   // protect previous iteration's reads

        // ---- stage A: sA <- tf32( W[kc+k][ib+m] ), fragment-shuffled --------
        {
            const int w = warp;              // mt = w  (m = w*16 + mm)
            const int l = lane;              // k local = l
            const int kt  = l >> 3;
            const int t4v = l & 3;
            const int khi = (l >> 2) & 1;
            const float* Wp = W + (size_t)(kc + l) * NNODES + ib;
#pragma unroll
            for (int mm = 0; mm < 16; mm++) {
                const int m = w * 16 + mm;
                float v = 0.f;
                if (ib + m < NNODES) v = Wp[m];
                const int g  = m & 7;
                const int hi = (m >> 3) & 1;
                const int lw = (((g << 2) | t4v)) ^ (kt << 3);
                const int r  = (khi << 1) | hi;
                sA[((kt * 8 + w) * 32 + lw) * 4 + r] = f2tf32(v);
            }
        }
        // ---- stage B: sB <- tf32( F[jb+j][kc+k] ), fragment-shuffled --------
        {
            const int j = tid >> 1;          // 0..127
            const int half = tid & 1;        // k-half (0:k<16, 1:k>=16)
            const int nt = j >> 3;
            const int g  = j & 7;
            const bool jv = (jb + j) < NNODES;
            const float* Fp = F + (size_t)(jb + j) * FDIM + kc + half * 16;
#pragma unroll
            for (int q = 0; q < 4; q++) {
                float4 v4 = make_float4(0.f, 0.f, 0.f, 0.f);
                if (jv) v4 = *(const float4*)(Fp + q * 4);
                float vv[4] = {v4.x, v4.y, v4.z, v4.w};
#pragma unroll
                for (int e = 0; e < 4; e++) {
                    const int k  = half * 16 + q * 4 + e;
                    const int kt = k >> 3;
                    const int kl = k & 7;
                    const int lw = (((g << 2) | (kl & 3))) ^ (kt << 3);
                    const int r  = kl >> 2;
                    sB[((kt * 16 + nt) * 32 + lw) * 2 + r] = f2tf32(vv[e]);
                }
            }
        }
        __syncthreads();

        // ---- compute: 4 k8-steps --------------------------------------------
#pragma unroll
        for (int kt = 0; kt < 4; kt++) {
            const int lx = lane ^ (kt << 3);
            uint32_t af[4][4];
#pragma unroll
            for (int mi = 0; mi < 4; mi++) {
                const uint4 v = *(const uint4*)&sA[((kt * 8 + wm * 4 + mi) * 32 + lx) * 4];
                af[mi][0] = v.x; af[mi][1] = v.y; af[mi][2] = v.z; af[mi][3] = v.w;
            }
            uint32_t bf[4][2];
#pragma unroll
            for (int ni = 0; ni < 4; ni++) {
                const uint2 v = *(const uint2*)&sB[((kt * 16 + wn * 4 + ni) * 32 + lx) * 2];
                bf[ni][0] = v.x; bf[ni][1] = v.y;
            }
#pragma unroll
            for (int mi = 0; mi < 4; mi++)
#pragma unroll
                for (int ni = 0; ni < 4; ni++)
                    mma_tf32(acc[mi][ni], af[mi], bf[ni]);
        }
    }

    // ---- epilogue: bias + relu + coalesced-ish float2 stores -----------------
    const int g  = lane >> 2;
    const int t4 = lane & 3;
#pragma unroll
    for (int mi = 0; mi < 4; mi++) {
        const int i0 = ib + (wm * 4 + mi) * 16 + g;
        const int i1 = i0 + 8;
        const float bv0 = (i0 < NNODES) ? bias[i0] : 0.f;
        const float bv1 = (i1 < NNODES) ? bias[i1] : 0.f;
#pragma unroll
        for (int ni = 0; ni < 4; ni++) {
            const int j = jb + (wn * 4 + ni) * 8 + t4 * 2;
            if (j < NNODES) {
                if (i0 < NNODES) {
                    float2 o;
                    o.x = fmaxf(acc[mi][ni][0] + bv0, 0.f);
                    o.y = fmaxf(acc[mi][ni][1] + bv0, 0.f);
                    *(float2*)&OUT[(size_t)i0 * NNODES + j] = o;
                }
                if (i1 < NNODES) {
                    float2 o;
                    o.x = fmaxf(acc[mi][ni][2] + bv1, 0.f);
                    o.y = fmaxf(acc[mi][ni][3] + bv1, 0.f);
                    *(float2*)&OUT[(size_t)i1 * NNODES + j] = o;
                }
            }
        }
    }
}

// ---------------- launch ------------------------------------------------------
extern "C" void kernel_launch(void* const* d_in, const int* in_sizes, int n_in,
                              void* d_out, int out_size) {
    const float* x   = (const float*)d_in[0];
    const int*   ei  = (const int*)d_in[1];
    const int*   src = ei;
    const int*   dst = ei + NEDGES;
    const float *Wl_e1 = (const float*)d_in[2],  *bl_e1 = (const float*)d_in[3],  *Wr_e1 = (const float*)d_in[4];
    const float *Wl_e2 = (const float*)d_in[5],  *bl_e2 = (const float*)d_in[6],  *Wr_e2 = (const float*)d_in[7];
    const float *Wl_a1 = (const float*)d_in[8],  *bl_a1 = (const float*)d_in[9],  *Wr_a1 = (const float*)d_in[10];
    const float *Wl_a2 = (const float*)d_in[11], *bl_a2 = (const float*)d_in[12], *Wr_a2 = (const float*)d_in[13];
    const float *Wl_s1 = (const float*)d_in[14], *bl_s1 = (const float*)d_in[15], *Wr_s1 = (const float*)d_in[16];
    const float *Wl_s2 = (const float*)d_in[17], *bl_s2 = (const float*)d_in[18], *Wr_s2 = (const float*)d_in[19];

    float* out    = (float*)d_out;
    float* xh_out = out + (size_t)NNODES * NNODES;

    float *pB1, *pB2, *pAGG;
    cudaGetSymbolAddress((void**)&pB1,  g_B1);
    cudaGetSymbolAddress((void**)&pB2,  g_B2);
    cudaGetSymbolAddress((void**)&pAGG, g_AGG);

    // CSR build
    zero_kernel<<<(NNODES + 255) / 256, 256>>>();
    count_kernel<<<(NEDGES + 255) / 256, 256>>>(dst);
    scan_kernel<<<1, 1024>>>();
    fill_kernel<<<(NEDGES + 255) / 256, 256>>>(src, dst);

    const int LG = (NNODES + 63) / 64;
    dim3 fg((NNODES + 127) / 128, (NNODES + 127) / 128);  // 79x79

    // encoder
    agg_kernel<<<NNODES, 128>>>(x);
    layer_kernel<<<LG, 128>>>(pAGG, x, Wl_e1, Wr_e1, bl_e1, pB1);      // h1
    agg_kernel<<<NNODES, 128>>>(pB1);
    layer_kernel<<<LG, 128>>>(pAGG, pB1, Wl_e2, Wr_e2, bl_e2, pB2);    // h2
    // attribute decoder
    agg_kernel<<<NNODES, 128>>>(pB2);
    layer_kernel<<<LG, 128>>>(pAGG, pB2, Wl_a1, Wr_a1, bl_a1, pB1);    // a1
    agg_kernel<<<NNODES, 128>>>(pB1);
    layer_kernel<<<LG, 128>>>(pAGG, pB1, Wl_a2, Wr_a2, bl_a2, xh_out); // xh
    // structure decoder
    agg_kernel<<<NNODES, 128>>>(pB2);
    layer_kernel<<<LG, 128>>>(pAGG, pB2, Wl_s1, Wr_s1, bl_s1, pB1);    // s1
    agg_kernel<<<NNODES, 128>>>(pB1);
    final_tc_kernel<<<fg, 256>>>(pAGG, pB1, Wl_s2, Wr_s2, bl_s2, out); // s (transposed)
}

// round 9
// speedup vs baseline: 3.7520x; 1.9624x over previous
#include <cuda_runtime.h>
#include <cstdint>
#include <cstddef>

#define NNODES 10000
#define NEDGES 320000
#define FDIM   128
#define NTILES 79            // ceil(10000/128)

// ---------------- device scratch (allocation-free rule: __device__ globals) ---
__device__ float g_B1[NNODES * FDIM];   // h1 / a1out / s1out
__device__ float g_B2[NNODES * FDIM];   // h2
__device__ float g_AGG[NNODES * FDIM];  // aggregation buffer (pre-scaled by 1/deg)
__device__ float g_inv[NNODES];
__device__ int   g_deg[NNODES];
__device__ int   g_cur[NNODES];
__device__ int   g_ptr[NNODES + 1];
__device__ int   g_csrc[NEDGES];
// pre-shuffled tf32 operands for the final GEMM: [tile][chunk][4096] u32
__device__ uint32_t g_Ashuf[NTILES * 8 * 4096];   // ~10.3 MB
__device__ uint32_t g_Bshuf[NTILES * 8 * 4096];   // ~10.3 MB

// ---------------- CSR construction -------------------------------------------
__global__ void zero_kernel() {
    int i = blockIdx.x * blockDim.x + threadIdx.x;
    if (i < NNODES) { g_deg[i] = 0; g_cur[i] = 0; }
}

__global__ void count_kernel(const int* __restrict__ dst) {
    int e = blockIdx.x * blockDim.x + threadIdx.x;
    if (e < NEDGES) atomicAdd(&g_deg[dst[e]], 1);
}

__global__ void scan_kernel() {
    __shared__ int sh[1024];
    int carry = 0;
    for (int base = 0; base < NNODES; base += 1024) {
        int i = base + threadIdx.x;
        int v = (i < NNODES) ? g_deg[i] : 0;
        sh[threadIdx.x] = v;
        __syncthreads();
        for (int off = 1; off < 1024; off <<= 1) {
            int t = (threadIdx.x >= off) ? sh[threadIdx.x - off] : 0;
            __syncthreads();
            sh[threadIdx.x] += t;
            __syncthreads();
        }
        if (i < NNODES) {
            g_ptr[i] = carry + sh[threadIdx.x] - v;           // exclusive
            g_inv[i] = 1.0f / fmaxf((float)v, 1.0f);
        }
        carry += sh[1023];
        __syncthreads();
    }
    if (threadIdx.x == 0) g_ptr[NNODES] = carry;
}

__global__ void fill_kernel(const int* __restrict__ src, const int* __restrict__ dst) {
    int e = blockIdx.x * blockDim.x + threadIdx.x;
    if (e < NEDGES) {
        int d = dst[e];
        int pos = g_ptr[d] + atomicAdd(&g_cur[d], 1);
        g_csrc[pos] = src[e];
    }
}

// ---------------- mean aggregation: one block (128 thr) per node --------------
__global__ void agg_kernel(const float* __restrict__ X) {
    int node = blockIdx.x;
    int t = threadIdx.x;
    int beg = g_ptr[node], end = g_ptr[node + 1];
    float s0 = 0.f, s1 = 0.f, s2 = 0.f, s3 = 0.f;
    int e = beg;
    for (; e + 4 <= end; e += 4) {
        int i0 = g_csrc[e], i1 = g_csrc[e + 1], i2 = g_csrc[e + 2], i3 = g_csrc[e + 3];
        s0 += X[i0 * FDIM + t];
        s1 += X[i1 * FDIM + t];
        s2 += X[i2 * FDIM + t];
        s3 += X[i3 * FDIM + t];
    }
    for (; e < end; e++) s0 += X[g_csrc[e] * FDIM + t];
    g_AGG[node * FDIM + t] = (s0 + s1 + s2 + s3) * g_inv[node];
}

// ---------------- fused SAGE layer: Y = relu(AGG@Wl + X@Wr + b), dout=128 -----
__global__ void layer_kernel(const float* __restrict__ A0,
                             const float* __restrict__ A1,
                             const float* __restrict__ W0,
                             const float* __restrict__ W1,
                             const float* __restrict__ bias,
                             float* __restrict__ Y) {
    __shared__ float As[8][64];
    __shared__ float Bs[8][128];
    int tid = threadIdx.x;
    int r0 = blockIdx.x * 64;

    float acc[8][8];
#pragma unroll
    for (int i = 0; i < 8; i++)
#pragma unroll
        for (int j = 0; j < 8; j++) acc[i][j] = 0.f;

    int lrow = tid >> 1;
    int lc   = (tid & 1) * 4;
    int rowb = (tid >> 4) * 8;
    int colb = (tid & 15) * 8;

    for (int phase = 0; phase < 2; phase++) {
        const float* A = phase ? A1 : A0;
        const float* W = phase ? W1 : W0;
        for (int k0 = 0; k0 < 128; k0 += 8) {
            float4 av = make_float4(0.f, 0.f, 0.f, 0.f);
            int grow = r0 + lrow;
            if (grow < NNODES) av = *(const float4*)&A[grow * FDIM + k0 + lc];
            As[lc + 0][lrow] = av.x;
            As[lc + 1][lrow] = av.y;
            As[lc + 2][lrow] = av.z;
            As[lc + 3][lrow] = av.w;
            {
                int idx = tid;
                int kk = idx >> 5, j4 = (idx & 31) * 4;
                *(float4*)&Bs[kk][j4] = *(const float4*)&W[(k0 + kk) * 128 + j4];
                idx = tid + 128;
                kk = idx >> 5; j4 = (idx & 31) * 4;
                *(float4*)&Bs[kk][j4] = *(const float4*)&W[(k0 + kk) * 128 + j4];
            }
            __syncthreads();
#pragma unroll
            for (int k = 0; k < 8; k++) {
                float a[8], b[8];
                *(float4*)&a[0] = *(const float4*)&As[k][rowb];
                *(float4*)&a[4] = *(const float4*)&As[k][rowb + 4];
                *(float4*)&b[0] = *(const float4*)&Bs[k][colb];
                *(float4*)&b[4] = *(const float4*)&Bs[k][colb + 4];
#pragma unroll
                for (int ii = 0; ii < 8; ii++)
#pragma unroll
                    for (int jj = 0; jj < 8; jj++) acc[ii][jj] += a[ii] * b[jj];
            }
            __syncthreads();
        }
    }
#pragma unroll
    for (int ii = 0; ii < 8; ii++) {
        int grow = r0 + rowb + ii;
        if (grow < NNODES) {
#pragma unroll
            for (int jj = 0; jj < 8; jj += 4) {
                float4 o;
                o.x = fmaxf(acc[ii][jj + 0] + bias[colb + jj + 0], 0.f);
                o.y = fmaxf(acc[ii][jj + 1] + bias[colb + jj + 1], 0.f);
                o.z = fmaxf(acc[ii][jj + 2] + bias[colb + jj + 2], 0.f);
                o.w = fmaxf(acc[ii][jj + 3] + bias[colb + jj + 3], 0.f);
                *(float4*)&Y[(size_t)grow * 128 + colb + jj] = o;
            }
        }
    }
}

// ================== tf32 mma.sync final GEMM (sm_80+ path) ===================
// OUT[i,j] = relu( sum_k Wl[k,i]*AGG[j,k] + sum_k Wr[k,i]*S1[j,k] + b[i] )
// Operands pre-converted to tf32 and pre-shuffled into per-(tile,chunk)
// contiguous 16KB fragment blocks by shufA/shufB kernels. Final kernel does
// contiguous cp.async staging, double-buffered, 8 warps, warp tile 64x32.
//
// Fragment mapping (m16n8k8, row.col):
//   A slot (kt,mt,lane,r): idx = ((kt*8+mt)*32 + (lane^(kt<<3)))*4 + r
//     element m = mt*16 + (lane>>2) + (r&1)*8 ; k = kt*8 + (lane&3) + (r>>1)*4
//   B slot (kt,nt,lane,r): idx = ((kt*16+nt)*32 + (lane^(kt<<3)))*2 + r
//     element n = nt*8 + (lane>>2) ; k = kt*8 + (lane&3) + r*4

__device__ __forceinline__ uint32_t f2tf32(float v) {
    uint32_t t;
    asm("cvt.rna.tf32.f32 %0, %1;" : "=r"(t) : "f"(v));
    return t;
}

__device__ __forceinline__ void mma_tf32(float* c, const uint32_t* a, const uint32_t* b) {
    asm volatile(
        "mma.sync.aligned.m16n8k8.row.col.f32.tf32.tf32.f32 "
        "{%0,%1,%2,%3}, {%4,%5,%6,%7}, {%8,%9}, {%0,%1,%2,%3};\n"
        : "+f"(c[0]), "+f"(c[1]), "+f"(c[2]), "+f"(c[3])
        : "r"(a[0]), "r"(a[1]), "r"(a[2]), "r"(a[3]),
          "r"(b[0]), "r"(b[1]));
}

__device__ __forceinline__ void cp16(uint32_t smem_addr, const void* gptr) {
    asm volatile("cp.async.ca.shared.global [%0], [%1], 16;"
                 :: "r"(smem_addr), "l"(gptr));
}

// ---- pre-shuffle A: weights W[k, i] -> fragment blocks ----------------------
__global__ void shufA_kernel(const float* __restrict__ Wl,
                             const float* __restrict__ Wr) {
    const int tile  = blockIdx.x;          // 0..78  (ib = tile*128)
    const int chunk = blockIdx.y;          // 0..7
    const int phase = chunk >> 2;
    const int kc    = (chunk & 3) * 32;
    const float* __restrict__ W = phase ? Wr : Wl;
    const int ib   = tile * 128;
    const int warp = threadIdx.x >> 5;     // mt = warp
    const int lane = threadIdx.x & 31;     // local k
    const int kt   = lane >> 3;
    const int t4v  = lane & 3;
    const int khi  = (lane >> 2) & 1;
    const float* Wp = W + (size_t)(kc + lane) * NNODES + ib;
    uint32_t* dst = g_Ashuf + (size_t)(tile * 8 + chunk) * 4096;
#pragma unroll
    for (int mm = 0; mm < 16; mm++) {
        const int m = warp * 16 + mm;
        float v = 0.f;
        if (ib + m < NNODES) v = Wp[m];
        const int g  = m & 7;
        const int hi = (m >> 3) & 1;
        const int lw = ((g << 2) | t4v) ^ (kt << 3);
        const int r  = (khi << 1) | hi;
        dst[((kt * 8 + warp) * 32 + lw) * 4 + r] = f2tf32(v);
    }
}

// ---- pre-shuffle B: features F[j, k] -> fragment blocks ---------------------
__global__ void shufB_kernel(const float* __restrict__ AGG,
                             const float* __restrict__ S1) {
    const int tile  = blockIdx.x;
    const int chunk = blockIdx.y;
    const int phase = chunk >> 2;
    const int kc    = (chunk & 3) * 32;
    const float* __restrict__ F = phase ? S1 : AGG;
    const int jb   = tile * 128;
    const int tid  = threadIdx.x;
    const int j    = tid >> 1;
    const int half = tid & 1;
    const int nt   = j >> 3;
    const int g    = j & 7;
    const bool jv  = (jb + j) < NNODES;
    const float* Fp = F + (size_t)(jb + j) * FDIM + kc + half * 16;
    uint32_t* dst = g_Bshuf + (size_t)(tile * 8 + chunk) * 4096;
#pragma unroll
    for (int q = 0; q < 4; q++) {
        float4 v4 = make_float4(0.f, 0.f, 0.f, 0.f);
        if (jv) v4 = *(const float4*)(Fp + q * 4);
        float vv[4] = {v4.x, v4.y, v4.z, v4.w};
#pragma unroll
        for (int e = 0; e < 4; e++) {
            const int k  = half * 16 + q * 4 + e;
            const int kt = k >> 3;
            const int kl = k & 7;
            const int lw = ((g << 2) | (kl & 3)) ^ (kt << 3);
            const int r  = kl >> 2;
            dst[((kt * 16 + nt) * 32 + lw) * 2 + r] = f2tf32(vv[e]);
        }
    }
}

// ---- final GEMM: cp.async double-buffered ------------------------------------
extern __shared__ uint32_t dynsmem[];   // [2][4096] A + [2][4096] B = 64KB

__global__ void __launch_bounds__(256, 2)
final_tc_kernel(const float* __restrict__ bias,  // [NNODES]
                float* __restrict__ OUT) {       // [NNODES, NNODES]
    uint32_t* sA = dynsmem;           // 2 x 4096
    uint32_t* sB = dynsmem + 8192;    // 2 x 4096

    const int tid  = threadIdx.x;
    const int lane = tid & 31;
    const int warp = tid >> 5;
    const int wm   = warp >> 2;       // 0..1
    const int wn   = warp & 3;        // 0..3
    const int ib   = blockIdx.y * 128;
    const int jb   = blockIdx.x * 128;

    const uint32_t* __restrict__ srcA = g_Ashuf + (size_t)blockIdx.y * 8 * 4096;
    const uint32_t* __restrict__ srcB = g_Bshuf + (size_t)blockIdx.x * 8 * 4096;

    float acc[4][4][4];
#pragma unroll
    for (int mi = 0; mi < 4; mi++)
#pragma unroll
        for (int ni = 0; ni < 4; ni++)
#pragma unroll
            for (int r = 0; r < 4; r++) acc[mi][ni][r] = 0.f;

    const uint32_t sA_u = (uint32_t)__cvta_generic_to_shared(sA);
    const uint32_t sB_u = (uint32_t)__cvta_generic_to_shared(sB);

    // issue one chunk's staging (32KB total: 8 cp.async x 16B per thread)
    auto issue = [&](int chunk) {
        const int buf = chunk & 1;
        const uint32_t* a = srcA + chunk * 4096;
        const uint32_t* b = srcB + chunk * 4096;
        const uint32_t sa = sA_u + buf * 4096 * 4;
        const uint32_t sb = sB_u + buf * 4096 * 4;
#pragma unroll
        for (int it = 0; it < 4; it++) {
            const int off = (tid + it * 256) * 4;     // u32 index, 16B granule
            cp16(sa + off * 4, a + off);
            cp16(sb + off * 4, b + off);
        }
        asm volatile("cp.async.commit_group;");
    };

    issue(0);
    for (int c = 0; c < 8; c++) {
        if (c < 7) {
            issue(c + 1);
            asm volatile("cp.async.wait_group 1;");
        } else {
            asm volatile("cp.async.wait_group 0;");
        }
        __syncthreads();

        const uint32_t* cA = sA + (c & 1) * 4096;
        const uint32_t* cB = sB + (c & 1) * 4096;
#pragma unroll
        for (int kt = 0; kt < 4; kt++) {
            const int lx = lane ^ (kt << 3);
            uint32_t af[4][4];
#pragma unroll
            for (int mi = 0; mi < 4; mi++) {
                const uint4 v = *(const uint4*)&cA[((kt * 8 + wm * 4 + mi) * 32 + lx) * 4];
                af[mi][0] = v.x; af[mi][1] = v.y; af[mi][2] = v.z; af[mi][3] = v.w;
            }
            uint32_t bf[4][2];
#pragma unroll
            for (int ni = 0; ni < 4; ni++) {
                const uint2 v = *(const uint2*)&cB[((kt * 16 + wn * 4 + ni) * 32 + lx) * 2];
                bf[ni][0] = v.x; bf[ni][1] = v.y;
            }
#pragma unroll
            for (int mi = 0; mi < 4; mi++)
#pragma unroll
                for (int ni = 0; ni < 4; ni++)
                    mma_tf32(acc[mi][ni], af[mi], bf[ni]);
        }
        __syncthreads();
    }

    // ---- epilogue: bias + relu + float2 stores -------------------------------
    const int g  = lane >> 2;
    const int t4 = lane & 3;
#pragma unroll
    for (int mi = 0; mi < 4; mi++) {
        const int i0 = ib + (wm * 4 + mi) * 16 + g;
        const int i1 = i0 + 8;
        const float bv0 = (i0 < NNODES) ? bias[i0] : 0.f;
        const float bv1 = (i1 < NNODES) ? bias[i1] : 0.f;
#pragma unroll
        for (int ni = 0; ni < 4; ni++) {
            const int j = jb + (wn * 4 + ni) * 8 + t4 * 2;
            if (j < NNODES) {
                if (i0 < NNODES) {
                    float2 o;
                    o.x = fmaxf(acc[mi][ni][0] + bv0, 0.f);
                    o.y = fmaxf(acc[mi][ni][1] + bv0, 0.f);
                    *(float2*)&OUT[(size_t)i0 * NNODES + j] = o;
                }
                if (i1 < NNODES) {
                    float2 o;
                    o.x = fmaxf(acc[mi][ni][2] + bv1, 0.f);
                    o.y = fmaxf(acc[mi][ni][3] + bv1, 0.f);
                    *(float2*)&OUT[(size_t)i1 * NNODES + j] = o;
                }
            }
        }
    }
}

// ---------------- launch ------------------------------------------------------
extern "C" void kernel_launch(void* const* d_in, const int* in_sizes, int n_in,
                              void* d_out, int out_size) {
    const float* x   = (const float*)d_in[0];
    const int*   ei  = (const int*)d_in[1];
    const int*   src = ei;
    const int*   dst = ei + NEDGES;
    const float *Wl_e1 = (const float*)d_in[2],  *bl_e1 = (const float*)d_in[3],  *Wr_e1 = (const float*)d_in[4];
    const float *Wl_e2 = (const float*)d_in[5],  *bl_e2 = (const float*)d_in[6],  *Wr_e2 = (const float*)d_in[7];
    const float *Wl_a1 = (const float*)d_in[8],  *bl_a1 = (const float*)d_in[9],  *Wr_a1 = (const float*)d_in[10];
    const float *Wl_a2 = (const float*)d_in[11], *bl_a2 = (const float*)d_in[12], *Wr_a2 = (const float*)d_in[13];
    const float *Wl_s1 = (const float*)d_in[14], *bl_s1 = (const float*)d_in[15], *Wr_s1 = (const float*)d_in[16];
    const float *Wl_s2 = (const float*)d_in[17], *bl_s2 = (const float*)d_in[18], *Wr_s2 = (const float*)d_in[19];

    float* out    = (float*)d_out;
    float* xh_out = out + (size_t)NNODES * NNODES;

    float *pB1, *pB2, *pAGG;
    cudaGetSymbolAddress((void**)&pB1,  g_B1);
    cudaGetSymbolAddress((void**)&pB2,  g_B2);
    cudaGetSymbolAddress((void**)&pAGG, g_AGG);

    static bool attr_set = false;
    if (!attr_set) {
        cudaFuncSetAttribute(final_tc_kernel,
                             cudaFuncAttributeMaxDynamicSharedMemorySize, 65536);
        attr_set = true;
    }

    // CSR build
    zero_kernel<<<(NNODES + 255) / 256, 256>>>();
    count_kernel<<<(NEDGES + 255) / 256, 256>>>(dst);
    scan_kernel<<<1, 1024>>>();
    fill_kernel<<<(NEDGES + 255) / 256, 256>>>(src, dst);

    const int LG = (NNODES + 63) / 64;
    dim3 fg((NNODES + 127) / 128, (NNODES + 127) / 128);  // 79x79
    dim3 sg(NTILES, 8);

    // pre-shuffle the final-layer weights (inputs, available immediately)
    shufA_kernel<<<sg, 256>>>(Wl_s2, Wr_s2);

    // encoder
    agg_kernel<<<NNODES, 128>>>(x);
    layer_kernel<<<LG, 128>>>(pAGG, x, Wl_e1, Wr_e1, bl_e1, pB1);      // h1
    agg_kernel<<<NNODES, 128>>>(pB1);
    layer_kernel<<<LG, 128>>>(pAGG, pB1, Wl_e2, Wr_e2, bl_e2, pB2);    // h2
    // attribute decoder
    agg_kernel<<<NNODES, 128>>>(pB2);
    layer_kernel<<<LG, 128>>>(pAGG, pB2, Wl_a1, Wr_a1, bl_a1, pB1);    // a1
    agg_kernel<<<NNODES, 128>>>(pB1);
    layer_kernel<<<LG, 128>>>(pAGG, pB1, Wl_a2, Wr_a2, bl_a2, xh_out); // xh
    // structure decoder
    agg_kernel<<<NNODES, 128>>>(pB2);
    layer_kernel<<<LG, 128>>>(pAGG, pB2, Wl_s1, Wr_s1, bl_s1, pB1);    // s1
    agg_kernel<<<NNODES, 128>>>(pB1);
    // pre-shuffle features for the final GEMM (AGG + S1=pB1)
    shufB_kernel<<<sg, 256>>>(pAGG, pB1);
    final_tc_kernel<<<fg, 256, 65536>>>(bl_s2, out);                   // s (transposed)
}

// round 10
// speedup vs baseline: 4.0394x; 1.0766x over previous
#include <cuda_runtime.h>
#include <cstdint>
#include <cstddef>

#define NNODES 10000
#define NEDGES 320000
#define FDIM   128
#define NTILES 79            // ceil(10000/128)

// ---------------- device scratch (allocation-free rule: __device__ globals) ---
__device__ float g_B1[NNODES * FDIM];   // h1 / s1out
__device__ float g_B2[NNODES * FDIM];   // h2
__device__ float g_B3[NNODES * FDIM];   // a1out (a-branch private)
__device__ float g_AGG[NNODES * FDIM];  // s-branch agg buffer
__device__ float g_AGG2[NNODES * FDIM]; // a-branch agg buffer
__device__ float g_inv[NNODES];
__device__ int   g_deg[NNODES];
__device__ int   g_cur[NNODES];
__device__ int   g_ptr[NNODES + 1];
__device__ int   g_csrc[NEDGES];
// pre-shuffled tf32 operands for the final GEMM: [tile][chunk][4096] u32
__device__ uint32_t g_Ashuf[NTILES * 8 * 4096];   // ~10.3 MB
__device__ uint32_t g_Bshuf[NTILES * 8 * 4096];   // ~10.3 MB

// ---------------- CSR construction -------------------------------------------
__global__ void zero_kernel() {
    int i = blockIdx.x * blockDim.x + threadIdx.x;
    if (i < NNODES) { g_deg[i] = 0; g_cur[i] = 0; }
}

__global__ void count_kernel(const int* __restrict__ dst) {
    int e = blockIdx.x * blockDim.x + threadIdx.x;
    if (e < NEDGES) atomicAdd(&g_deg[dst[e]], 1);
}

__global__ void scan_kernel() {
    __shared__ int sh[1024];
    int carry = 0;
    for (int base = 0; base < NNODES; base += 1024) {
        int i = base + threadIdx.x;
        int v = (i < NNODES) ? g_deg[i] : 0;
        sh[threadIdx.x] = v;
        __syncthreads();
        for (int off = 1; off < 1024; off <<= 1) {
            int t = (threadIdx.x >= off) ? sh[threadIdx.x - off] : 0;
            __syncthreads();
            sh[threadIdx.x] += t;
            __syncthreads();
        }
        if (i < NNODES) {
            g_ptr[i] = carry + sh[threadIdx.x] - v;           // exclusive
            g_inv[i] = 1.0f / fmaxf((float)v, 1.0f);
        }
        carry += sh[1023];
        __syncthreads();
    }
    if (threadIdx.x == 0) g_ptr[NNODES] = carry;
}

__global__ void fill_kernel(const int* __restrict__ src, const int* __restrict__ dst) {
    int e = blockIdx.x * blockDim.x + threadIdx.x;
    if (e < NEDGES) {
        int d = dst[e];
        int pos = g_ptr[d] + atomicAdd(&g_cur[d], 1);
        g_csrc[pos] = src[e];
    }
}

// ---------------- mean aggregation: one WARP per node, float4 lanes -----------
__global__ void agg_kernel(const float* __restrict__ X, float* __restrict__ O) {
    const int gw   = (blockIdx.x * blockDim.x + threadIdx.x) >> 5;  // node
    const int lane = threadIdx.x & 31;
    if (gw >= NNODES) return;
    const float4* __restrict__ Xv = (const float4*)X;   // 32 float4 per row
    const int beg = g_ptr[gw], end = g_ptr[gw + 1];
    float4 a0 = make_float4(0.f, 0.f, 0.f, 0.f);
    float4 a1 = make_float4(0.f, 0.f, 0.f, 0.f);
    float4 a2 = make_float4(0.f, 0.f, 0.f, 0.f);
    float4 a3 = make_float4(0.f, 0.f, 0.f, 0.f);
    int e = beg;
    for (; e + 4 <= end; e += 4) {
        const int i0 = g_csrc[e], i1 = g_csrc[e + 1];
        const int i2 = g_csrc[e + 2], i3 = g_csrc[e + 3];
        const float4 v0 = Xv[i0 * 32 + lane];
        const float4 v1 = Xv[i1 * 32 + lane];
        const float4 v2 = Xv[i2 * 32 + lane];
        const float4 v3 = Xv[i3 * 32 + lane];
        a0.x += v0.x; a0.y += v0.y; a0.z += v0.z; a0.w += v0.w;
        a1.x += v1.x; a1.y += v1.y; a1.z += v1.z; a1.w += v1.w;
        a2.x += v2.x; a2.y += v2.y; a2.z += v2.z; a2.w += v2.w;
        a3.x += v3.x; a3.y += v3.y; a3.z += v3.z; a3.w += v3.w;
    }
    for (; e < end; e++) {
        const float4 v = Xv[g_csrc[e] * 32 + lane];
        a0.x += v.x; a0.y += v.y; a0.z += v.z; a0.w += v.w;
    }
    const float inv = g_inv[gw];
    float4 o;
    o.x = (a0.x + a1.x + a2.x + a3.x) * inv;
    o.y = (a0.y + a1.y + a2.y + a3.y) * inv;
    o.z = (a0.z + a1.z + a2.z + a3.z) * inv;
    o.w = (a0.w + a1.w + a2.w + a3.w) * inv;
    ((float4*)O)[gw * 32 + lane] = o;
}
#define AGG_GRID ((NNODES * 32 + 255) / 256)

// ---------------- fused SAGE layer: Y = relu(AGG@Wl + X@Wr + b), dout=128 -----
// BM=64 x BN=128, 256 threads (8 warps), 4x8 microtile, BK=8, 2 K-phases.
__global__ void __launch_bounds__(256)
layer_kernel(const float* __restrict__ A0,
             const float* __restrict__ A1,
             const float* __restrict__ W0,
             const float* __restrict__ W1,
             const float* __restrict__ bias,
             float* __restrict__ Y) {
    __shared__ float As[8][64];
    __shared__ float Bs[8][128];
    int tid = threadIdx.x;
    int r0 = blockIdx.x * 64;

    float acc[4][8];
#pragma unroll
    for (int i = 0; i < 4; i++)
#pragma unroll
        for (int j = 0; j < 8; j++) acc[i][j] = 0.f;

    int rowb = (tid >> 4) * 4;      // 0..60
    int colb = (tid & 15) * 8;      // 0..120

    for (int phase = 0; phase < 2; phase++) {
        const float* A = phase ? A1 : A0;
        const float* W = phase ? W1 : W0;
        for (int k0 = 0; k0 < 128; k0 += 8) {
            if (tid < 128) {        // A tile: 64 rows x 8 k, transposed
                int lrow = tid >> 1;
                int lc   = (tid & 1) * 4;
                float4 av = make_float4(0.f, 0.f, 0.f, 0.f);
                int grow = r0 + lrow;
                if (grow < NNODES) av = *(const float4*)&A[grow * FDIM + k0 + lc];
                As[lc + 0][lrow] = av.x;
                As[lc + 1][lrow] = av.y;
                As[lc + 2][lrow] = av.z;
                As[lc + 3][lrow] = av.w;
            }
            {                        // B tile: 8 k x 128 cols, one float4/thread
                int kk = tid >> 5, j4 = (tid & 31) * 4;
                *(float4*)&Bs[kk][j4] = *(const float4*)&W[(k0 + kk) * 128 + j4];
            }
            __syncthreads();
#pragma unroll
            for (int k = 0; k < 8; k++) {
                float a[4], b[8];
                *(float4*)&a[0] = *(const float4*)&As[k][rowb];
                *(float4*)&b[0] = *(const float4*)&Bs[k][colb];
                *(float4*)&b[4] = *(const float4*)&Bs[k][colb + 4];
#pragma unroll
                for (int ii = 0; ii < 4; ii++)
#pragma unroll
                    for (int jj = 0; jj < 8; jj++) acc[ii][jj] += a[ii] * b[jj];
            }
            __syncthreads();
        }
    }
#pragma unroll
    for (int ii = 0; ii < 4; ii++) {
        int grow = r0 + rowb + ii;
        if (grow < NNODES) {
#pragma unroll
            for (int jj = 0; jj < 8; jj += 4) {
                float4 o;
                o.x = fmaxf(acc[ii][jj + 0] + bias[colb + jj + 0], 0.f);
                o.y = fmaxf(acc[ii][jj + 1] + bias[colb + jj + 1], 0.f);
                o.z = fmaxf(acc[ii][jj + 2] + bias[colb + jj + 2], 0.f);
                o.w = fmaxf(acc[ii][jj + 3] + bias[colb + jj + 3], 0.f);
                *(float4*)&Y[(size_t)grow * 128 + colb + jj] = o;
            }
        }
    }
}

// ================== tf32 mma.sync final GEMM (sm_80+ path) ===================
__device__ __forceinline__ uint32_t f2tf32(float v) {
    uint32_t t;
    asm("cvt.rna.tf32.f32 %0, %1;" : "=r"(t) : "f"(v));
    return t;
}

__device__ __forceinline__ void mma_tf32(float* c, const uint32_t* a, const uint32_t* b) {
    asm volatile(
        "mma.sync.aligned.m16n8k8.row.col.f32.tf32.tf32.f32 "
        "{%0,%1,%2,%3}, {%4,%5,%6,%7}, {%8,%9}, {%0,%1,%2,%3};\n"
        : "+f"(c[0]), "+f"(c[1]), "+f"(c[2]), "+f"(c[3])
        : "r"(a[0]), "r"(a[1]), "r"(a[2]), "r"(a[3]),
          "r"(b[0]), "r"(b[1]));
}

__device__ __forceinline__ void cp16(uint32_t smem_addr, const void* gptr) {
    asm volatile("cp.async.ca.shared.global [%0], [%1], 16;"
                 :: "r"(smem_addr), "l"(gptr));
}

// ---- pre-shuffle A: weights W[k, i] -> fragment blocks ----------------------
__global__ void shufA_kernel(const float* __restrict__ Wl,
                             const float* __restrict__ Wr) {
    const int tile  = blockIdx.x;          // 0..78  (ib = tile*128)
    const int chunk = blockIdx.y;          // 0..7
    const int phase = chunk >> 2;
    const int kc    = (chunk & 3) * 32;
    const float* __restrict__ W = phase ? Wr : Wl;
    const int ib   = tile * 128;
    const int warp = threadIdx.x >> 5;     // mt = warp
    const int lane = threadIdx.x & 31;     // local k
    const int kt   = lane >> 3;
    const int t4v  = lane & 3;
    const int khi  = (lane >> 2) & 1;
    const float* Wp = W + (size_t)(kc + lane) * NNODES + ib;
    uint32_t* dst = g_Ashuf + (size_t)(tile * 8 + chunk) * 4096;
#pragma unroll
    for (int mm = 0; mm < 16; mm++) {
        const int m = warp * 16 + mm;
        float v = 0.f;
        if (ib + m < NNODES) v = Wp[m];
        const int g  = m & 7;
        const int hi = (m >> 3) & 1;
        const int lw = ((g << 2) | t4v) ^ (kt << 3);
        const int r  = (khi << 1) | hi;
        dst[((kt * 8 + warp) * 32 + lw) * 4 + r] = f2tf32(v);
    }
}

// ---- pre-shuffle B: features F[j, k] -> fragment blocks ---------------------
__global__ void shufB_kernel(const float* __restrict__ AGG,
                             const float* __restrict__ S1) {
    const int tile  = blockIdx.x;
    const int chunk = blockIdx.y;
    const int phase = chunk >> 2;
    const int kc    = (chunk & 3) * 32;
    const float* __restrict__ F = phase ? S1 : AGG;
    const int jb   = tile * 128;
    const int tid  = threadIdx.x;
    const int j    = tid >> 1;
    const int half = tid & 1;
    const int nt   = j >> 3;
    const int g    = j & 7;
    const bool jv  = (jb + j) < NNODES;
    const float* Fp = F + (size_t)(jb + j) * FDIM + kc + half * 16;
    uint32_t* dst = g_Bshuf + (size_t)(tile * 8 + chunk) * 4096;
#pragma unroll
    for (int q = 0; q < 4; q++) {
        float4 v4 = make_float4(0.f, 0.f, 0.f, 0.f);
        if (jv) v4 = *(const float4*)(Fp + q * 4);
        float vv[4] = {v4.x, v4.y, v4.z, v4.w};
#pragma unroll
        for (int e = 0; e < 4; e++) {
            const int k  = half * 16 + q * 4 + e;
            const int kt = k >> 3;
            const int kl = k & 7;
            const int lw = ((g << 2) | (kl & 3)) ^ (kt << 3);
            const int r  = kl >> 2;
            dst[((kt * 16 + nt) * 32 + lw) * 2 + r] = f2tf32(vv[e]);
        }
    }
}

// ---- final GEMM: cp.async double-buffered ------------------------------------
extern __shared__ uint32_t dynsmem[];   // [2][4096] A + [2][4096] B = 64KB

__global__ void __launch_bounds__(256, 2)
final_tc_kernel(const float* __restrict__ bias,  // [NNODES]
                float* __restrict__ OUT) {       // [NNODES, NNODES]
    uint32_t* sA = dynsmem;           // 2 x 4096
    uint32_t* sB = dynsmem + 8192;    // 2 x 4096

    const int tid  = threadIdx.x;
    const int lane = tid & 31;
    const int warp = tid >> 5;
    const int wm   = warp >> 2;       // 0..1
    const int wn   = warp & 3;        // 0..3
    const int ib   = blockIdx.y * 128;
    const int jb   = blockIdx.x * 128;

    const uint32_t* __restrict__ srcA = g_Ashuf + (size_t)blockIdx.y * 8 * 4096;
    const uint32_t* __restrict__ srcB = g_Bshuf + (size_t)blockIdx.x * 8 * 4096;

    float acc[4][4][4];
#pragma unroll
    for (int mi = 0; mi < 4; mi++)
#pragma unroll
        for (int ni = 0; ni < 4; ni++)
#pragma unroll
            for (int r = 0; r < 4; r++) acc[mi][ni][r] = 0.f;

    const uint32_t sA_u = (uint32_t)__cvta_generic_to_shared(sA);
    const uint32_t sB_u = (uint32_t)__cvta_generic_to_shared(sB);

    auto issue = [&](int chunk) {
        const int buf = chunk & 1;
        const uint32_t* a = srcA + chunk * 4096;
        const uint32_t* b = srcB + chunk * 4096;
        const uint32_t sa = sA_u + buf * 4096 * 4;
        const uint32_t sb = sB_u + buf * 4096 * 4;
#pragma unroll
        for (int it = 0; it < 4; it++) {
            const int off = (tid + it * 256) * 4;     // u32 index, 16B granule
            cp16(sa + off * 4, a + off);
            cp16(sb + off * 4, b + off);
        }
        asm volatile("cp.async.commit_group;");
    };

    issue(0);
    for (int c = 0; c < 8; c++) {
        if (c < 7) {
            issue(c + 1);
            asm volatile("cp.async.wait_group 1;");
        } else {
            asm volatile("cp.async.wait_group 0;");
        }
        __syncthreads();

        const uint32_t* cA = sA + (c & 1) * 4096;
        const uint32_t* cB = sB + (c & 1) * 4096;
#pragma unroll
        for (int kt = 0; kt < 4; kt++) {
            const int lx = lane ^ (kt << 3);
            uint32_t af[4][4];
#pragma unroll
            for (int mi = 0; mi < 4; mi++) {
                const uint4 v = *(const uint4*)&cA[((kt * 8 + wm * 4 + mi) * 32 + lx) * 4];
                af[mi][0] = v.x; af[mi][1] = v.y; af[mi][2] = v.z; af[mi][3] = v.w;
            }
            uint32_t bf[4][2];
#pragma unroll
            for (int ni = 0; ni < 4; ni++) {
                const uint2 v = *(const uint2*)&cB[((kt * 16 + wn * 4 + ni) * 32 + lx) * 2];
                bf[ni][0] = v.x; bf[ni][1] = v.y;
            }
#pragma unroll
            for (int mi = 0; mi < 4; mi++)
#pragma unroll
                for (int ni = 0; ni < 4; ni++)
                    mma_tf32(acc[mi][ni], af[mi], bf[ni]);
        }
        __syncthreads();
    }

    // ---- epilogue: bias + relu + float2 stores -------------------------------
    const int g  = lane >> 2;
    const int t4 = lane & 3;
#pragma unroll
    for (int mi = 0; mi < 4; mi++) {
        const int i0 = ib + (wm * 4 + mi) * 16 + g;
        const int i1 = i0 + 8;
        const float bv0 = (i0 < NNODES) ? bias[i0] : 0.f;
        const float bv1 = (i1 < NNODES) ? bias[i1] : 0.f;
#pragma unroll
        for (int ni = 0; ni < 4; ni++) {
            const int j = jb + (wn * 4 + ni) * 8 + t4 * 2;
            if (j < NNODES) {
                if (i0 < NNODES) {
                    float2 o;
                    o.x = fmaxf(acc[mi][ni][0] + bv0, 0.f);
                    o.y = fmaxf(acc[mi][ni][1] + bv0, 0.f);
                    *(float2*)&OUT[(size_t)i0 * NNODES + j] = o;
                }
                if (i1 < NNODES) {
                    float2 o;
                    o.x = fmaxf(acc[mi][ni][2] + bv1, 0.f);
                    o.y = fmaxf(acc[mi][ni][3] + bv1, 0.f);
                    *(float2*)&OUT[(size_t)i1 * NNODES + j] = o;
                }
            }
        }
    }
}

// ---------------- launch ------------------------------------------------------
extern "C" void kernel_launch(void* const* d_in, const int* in_sizes, int n_in,
                              void* d_out, int out_size) {
    const float* x   = (const float*)d_in[0];
    const int*   ei  = (const int*)d_in[1];
    const int*   src = ei;
    const int*   dst = ei + NEDGES;
    const float *Wl_e1 = (const float*)d_in[2],  *bl_e1 = (const float*)d_in[3],  *Wr_e1 = (const float*)d_in[4];
    const float *Wl_e2 = (const float*)d_in[5],  *bl_e2 = (const float*)d_in[6],  *Wr_e2 = (const float*)d_in[7];
    const float *Wl_a1 = (const float*)d_in[8],  *bl_a1 = (const float*)d_in[9],  *Wr_a1 = (const float*)d_in[10];
    const float *Wl_a2 = (const float*)d_in[11], *bl_a2 = (const float*)d_in[12], *Wr_a2 = (const float*)d_in[13];
    const float *Wl_s1 = (const float*)d_in[14], *bl_s1 = (const float*)d_in[15], *Wr_s1 = (const float*)d_in[16];
    const float *Wl_s2 = (const float*)d_in[17], *bl_s2 = (const float*)d_in[18], *Wr_s2 = (const float*)d_in[19];

    float* out    = (float*)d_out;
    float* xh_out = out + (size_t)NNODES * NNODES;

    float *pB1, *pB2, *pB3, *pAGG, *pAGG2;
    cudaGetSymbolAddress((void**)&pB1,   g_B1);
    cudaGetSymbolAddress((void**)&pB2,   g_B2);
    cudaGetSymbolAddress((void**)&pB3,   g_B3);
    cudaGetSymbolAddress((void**)&pAGG,  g_AGG);
    cudaGetSymbolAddress((void**)&pAGG2, g_AGG2);

    // one-time resources (created on the uncaptured correctness call)
    static cudaStream_t s_a = nullptr;
    static cudaEvent_t ev_fork = nullptr, ev_join = nullptr;
    if (!s_a) {
        cudaStreamCreateWithFlags(&s_a, cudaStreamNonBlocking);
        cudaEventCreateWithFlags(&ev_fork, cudaEventDisableTiming);
        cudaEventCreateWithFlags(&ev_join, cudaEventDisableTiming);
        cudaFuncSetAttribute(final_tc_kernel,
                             cudaFuncAttributeMaxDynamicSharedMemorySize, 65536);
    }

    const int LG = (NNODES + 63) / 64;                    // 157 blocks
    dim3 fg((NNODES + 127) / 128, (NNODES + 127) / 128);  // 79x79
    dim3 sg(NTILES, 8);

    // pre-shuffle final-layer weights (pure input dependency)
    shufA_kernel<<<sg, 256>>>(Wl_s2, Wr_s2);

    // CSR build
    zero_kernel<<<(NNODES + 255) / 256, 256>>>();
    count_kernel<<<(NEDGES + 255) / 256, 256>>>(dst);
    scan_kernel<<<1, 1024>>>();
    fill_kernel<<<(NEDGES + 255) / 256, 256>>>(src, dst);

    // encoder (shared prefix)
    agg_kernel<<<AGG_GRID, 256>>>(x, pAGG);
    layer_kernel<<<LG, 256>>>(pAGG, x, Wl_e1, Wr_e1, bl_e1, pB1);       // h1
    agg_kernel<<<AGG_GRID, 256>>>(pB1, pAGG);
    layer_kernel<<<LG, 256>>>(pAGG, pB1, Wl_e2, Wr_e2, bl_e2, pB2);     // h2

    // fork: attribute decoder on side stream (independent of s-branch)
    cudaEventRecord(ev_fork, 0);
    cudaStreamWaitEvent(s_a, ev_fork, 0);
    agg_kernel<<<AGG_GRID, 256, 0, s_a>>>(pB2, pAGG2);
    layer_kernel<<<LG, 256, 0, s_a>>>(pAGG2, pB2, Wl_a1, Wr_a1, bl_a1, pB3);   // a1
    agg_kernel<<<AGG_GRID, 256, 0, s_a>>>(pB3, pAGG2);
    layer_kernel<<<LG, 256, 0, s_a>>>(pAGG2, pB3, Wl_a2, Wr_a2, bl_a2, xh_out);// xh
    cudaEventRecord(ev_join, s_a);

    // structure decoder + final GEMM on main stream
    agg_kernel<<<AGG_GRID, 256>>>(pB2, pAGG);
    layer_kernel<<<LG, 256>>>(pAGG, pB2, Wl_s1, Wr_s1, bl_s1, pB1);     // s1
    agg_kernel<<<AGG_GRID, 256>>>(pB1, pAGG);
    shufB_kernel<<<sg, 256>>>(pAGG, pB1);
    final_tc_kernel<<<fg, 256, 65536>>>(bl_s2, out);                    // s

    // join a-branch before capture ends
    cudaStreamWaitEvent(0, ev_join, 0);
}

// round 12
// speedup vs baseline: 4.3516x; 1.0773x over previous
#include <cuda_runtime.h>
#include <cstdint>
#include <cstddef>

#define NNODES 10000
#define NEDGES 320000
#define FDIM   128
#define NTILES 79            // ceil(10000/128)

// ---------------- device scratch (allocation-free rule: __device__ globals) ---
__device__ float g_B1[NNODES * FDIM];   // h1 / s1out
__device__ float g_B2[NNODES * FDIM];   // h2
__device__ float g_B3[NNODES * FDIM];   // a1out (a-branch private)
__device__ float g_AGG[NNODES * FDIM];  // s-branch agg buffer (e1/e2/s1 inputs)
__device__ float g_AGG2[NNODES * FDIM]; // a-branch agg buffer
__device__ float g_inv[NNODES];
__device__ int   g_deg[NNODES];
__device__ int   g_cur[NNODES];
__device__ int   g_ptr[NNODES + 1];
__device__ int   g_csrc[NEDGES];
// pre-shuffled tf32 operands for the final GEMM: [tile][chunk][4096] u32
// zero-initialized BSS; padding slots are only ever written zero -> stay zero.
__device__ uint32_t g_Ashuf[NTILES * 8 * 4096];   // ~10.3 MB
__device__ uint32_t g_Bshuf[NTILES * 8 * 4096];   // ~10.3 MB

// ---------------- CSR construction -------------------------------------------
__global__ void zero_kernel() {
    int i = blockIdx.x * blockDim.x + threadIdx.x;
    if (i < NNODES) { g_deg[i] = 0; g_cur[i] = 0; }
}

__global__ void count_kernel(const int* __restrict__ dst) {
    int e = blockIdx.x * blockDim.x + threadIdx.x;
    if (e < NEDGES) atomicAdd(&g_deg[dst[e]], 1);
}

// fast single-block scan: 1024 thr x 10 elems, shfl warp scans (~3us)
__global__ void __launch_bounds__(1024) scan_kernel() {
    __shared__ int wtot[32];
    const int tid  = threadIdx.x;
    const int lane = tid & 31, wid = tid >> 5;
    const int base = tid * 10;
    int v[10];
    int loc[10];
    int tot = 0;
#pragma unroll
    for (int i = 0; i < 10; i++) {
        v[i] = (base + i < NNODES) ? g_deg[base + i] : 0;
        loc[i] = tot;
        tot += v[i];
    }
    int inc = tot;
#pragma unroll
    for (int off = 1; off < 32; off <<= 1) {
        int t = __shfl_up_sync(0xffffffffu, inc, off);
        if (lane >= off) inc += t;
    }
    if (lane == 31) wtot[wid] = inc;
    __syncthreads();
    if (wid == 0) {
        int w = wtot[lane];
#pragma unroll
        for (int off = 1; off < 32; off <<= 1) {
            int t = __shfl_up_sync(0xffffffffu, w, off);
            if (lane >= off) w += t;
        }
        wtot[lane] = w;   // inclusive warp totals
    }
    __syncthreads();
    const int offset = inc - tot + (wid > 0 ? wtot[wid - 1] : 0);  // exclusive
#pragma unroll
    for (int i = 0; i < 10; i++) {
        const int idx = base + i;
        if (idx < NNODES) {
            g_ptr[idx] = offset + loc[i];
            g_inv[idx] = 1.0f / fmaxf((float)v[i], 1.0f);
        }
    }
    if (tid == 1023) g_ptr[NNODES] = offset + tot;
}

__global__ void fill_kernel(const int* __restrict__ src, const int* __restrict__ dst) {
    int e = blockIdx.x * blockDim.x + threadIdx.x;
    if (e < NEDGES) {
        int d = dst[e];
        int pos = g_ptr[d] + atomicAdd(&g_cur[d], 1);
        g_csrc[pos] = src[e];
    }
}

// ---------------- mean aggregation: one WARP per node, float4 lanes -----------
__global__ void agg_kernel(const float* __restrict__ X, float* __restrict__ O) {
    const int gw   = (blockIdx.x * blockDim.x + threadIdx.x) >> 5;  // node
    const int lane = threadIdx.x & 31;
    if (gw >= NNODES) return;
    const float4* __restrict__ Xv = (const float4*)X;   // 32 float4 per row
    const int beg = g_ptr[gw], end = g_ptr[gw + 1];
    float4 a0 = make_float4(0.f, 0.f, 0.f, 0.f);
    float4 a1 = make_float4(0.f, 0.f, 0.f, 0.f);
    float4 a2 = make_float4(0.f, 0.f, 0.f, 0.f);
    float4 a3 = make_float4(0.f, 0.f, 0.f, 0.f);
    int e = beg;
    for (; e + 4 <= end; e += 4) {
        const int i0 = g_csrc[e], i1 = g_csrc[e + 1];
        const int i2 = g_csrc[e + 2], i3 = g_csrc[e + 3];
        const float4 v0 = Xv[i0 * 32 + lane];
        const float4 v1 = Xv[i1 * 32 + lane];
        const float4 v2 = Xv[i2 * 32 + lane];
        const float4 v3 = Xv[i3 * 32 + lane];
        a0.x += v0.x; a0.y += v0.y; a0.z += v0.z; a0.w += v0.w;
        a1.x += v1.x; a1.y += v1.y; a1.z += v1.z; a1.w += v1.w;
        a2.x += v2.x; a2.y += v2.y; a2.z += v2.z; a2.w += v2.w;
        a3.x += v3.x; a3.y += v3.y; a3.z += v3.z; a3.w += v3.w;
    }
    for (; e < end; e++) {
        const float4 v = Xv[g_csrc[e] * 32 + lane];
        a0.x += v.x; a0.y += v.y; a0.z += v.z; a0.w += v.w;
    }
    const float inv = g_inv[gw];
    float4 o;
    o.x = (a0.x + a1.x + a2.x + a3.x) * inv;
    o.y = (a0.y + a1.y + a2.y + a3.y) * inv;
    o.z = (a0.z + a1.z + a2.z + a3.z) * inv;
    o.w = (a0.w + a1.w + a2.w + a3.w) * inv;
    ((float4*)O)[gw * 32 + lane] = o;
}
#define AGG_GRID ((NNODES * 32 + 255) / 256)

__device__ __forceinline__ uint32_t f2tf32(float v) {
    uint32_t t;
    asm("cvt.rna.tf32.f32 %0, %1;" : "=r"(t) : "f"(v));
    return t;
}

// ---- fused: final aggregation -> shuffled B chunks 0-3 directly --------------
__global__ void agg_shuf_kernel(const float* __restrict__ X) {
    const int gw   = (blockIdx.x * blockDim.x + threadIdx.x) >> 5;  // node j
    const int lane = threadIdx.x & 31;
    if (gw >= NNODES) return;
    const float4* __restrict__ Xv = (const float4*)X;
    const int beg = g_ptr[gw], end = g_ptr[gw + 1];
    float4 a0 = make_float4(0.f, 0.f, 0.f, 0.f);
    float4 a1 = make_float4(0.f, 0.f, 0.f, 0.f);
    float4 a2 = make_float4(0.f, 0.f, 0.f, 0.f);
    float4 a3 = make_float4(0.f, 0.f, 0.f, 0.f);
    int e = beg;
    for (; e + 4 <= end; e += 4) {
        const int i0 = g_csrc[e], i1 = g_csrc[e + 1];
        const int i2 = g_csrc[e + 2], i3 = g_csrc[e + 3];
        const float4 v0 = Xv[i0 * 32 + lane];
        const float4 v1 = Xv[i1 * 32 + lane];
        const float4 v2 = Xv[i2 * 32 + lane];
        const float4 v3 = Xv[i3 * 32 + lane];
        a0.x += v0.x; a0.y += v0.y; a0.z += v0.z; a0.w += v0.w;
        a1.x += v1.x; a1.y += v1.y; a1.z += v1.z; a1.w += v1.w;
        a2.x += v2.x; a2.y += v2.y; a2.z += v2.z; a2.w += v2.w;
        a3.x += v3.x; a3.y += v3.y; a3.z += v3.z; a3.w += v3.w;
    }
    for (; e < end; e++) {
        const float4 v = Xv[g_csrc[e] * 32 + lane];
        a0.x += v.x; a0.y += v.y; a0.z += v.z; a0.w += v.w;
    }
    const float inv = g_inv[gw];
    float ov[4];
    ov[0] = (a0.x + a1.x + a2.x + a3.x) * inv;
    ov[1] = (a0.y + a1.y + a2.y + a3.y) * inv;
    ov[2] = (a0.z + a1.z + a2.z + a3.z) * inv;
    ov[3] = (a0.w + a1.w + a2.w + a3.w) * inv;
    // scatter into fragment-shuffled B layout (phase 0 = chunks 0..3)
    const int tile  = gw >> 7;
    const int jloc  = gw & 127;
    const int nt    = jloc >> 3;
    const int g     = jloc & 7;
    const int chunk = lane >> 3;                    // k = 4*lane+e, chunk = k>>5
    uint32_t* dst = g_Bshuf + (size_t)(tile * 8 + chunk) * 4096;
#pragma unroll
    for (int e2 = 0; e2 < 4; e2++) {
        const int k  = 4 * lane + e2;
        const int kl2 = k & 31;                     // k within chunk
        const int kt = kl2 >> 3;
        const int kl = kl2 & 7;
        const int lw = ((g << 2) | (kl & 3)) ^ (kt << 3);
        const int r  = kl >> 2;
        dst[((kt * 16 + nt) * 32 + lw) * 2 + r] = f2tf32(ov[e2]);
    }
}

// ---------------- fused SAGE layer: Y = relu(AGG@Wl + X@Wr + b), dout=128 -----
__global__ void __launch_bounds__(256)
layer_kernel(const float* __restrict__ A0,
             const float* __restrict__ A1,
             const float* __restrict__ W0,
             const float* __restrict__ W1,
             const float* __restrict__ bias,
             float* __restrict__ Y) {
    __shared__ float As[8][64];
    __shared__ float Bs[8][128];
    int tid = threadIdx.x;
    int r0 = blockIdx.x * 64;

    float acc[4][8];
#pragma unroll
    for (int i = 0; i < 4; i++)
#pragma unroll
        for (int j = 0; j < 8; j++) acc[i][j] = 0.f;

    int rowb = (tid >> 4) * 4;      // 0..60
    int colb = (tid & 15) * 8;      // 0..120

    for (int phase = 0; phase < 2; phase++) {
        const float* A = phase ? A1 : A0;
        const float* W = phase ? W1 : W0;
        for (int k0 = 0; k0 < 128; k0 += 8) {
            if (tid < 128) {        // A tile: 64 rows x 8 k, transposed
                int lrow = tid >> 1;
                int lc   = (tid & 1) * 4;
                float4 av = make_float4(0.f, 0.f, 0.f, 0.f);
                int grow = r0 + lrow;
                if (grow < NNODES) av = *(const float4*)&A[grow * FDIM + k0 + lc];
                As[lc + 0][lrow] = av.x;
                As[lc + 1][lrow] = av.y;
                As[lc + 2][lrow] = av.z;
                As[lc + 3][lrow] = av.w;
            }
            {                        // B tile: 8 k x 128 cols, one float4/thread
                int kk = tid >> 5, j4 = (tid & 31) * 4;
                *(float4*)&Bs[kk][j4] = *(const float4*)&W[(k0 + kk) * 128 + j4];
            }
            __syncthreads();
#pragma unroll
            for (int k = 0; k < 8; k++) {
                float a[4], b[8];
                *(float4*)&a[0] = *(const float4*)&As[k][rowb];
                *(float4*)&b[0] = *(const float4*)&Bs[k][colb];
                *(float4*)&b[4] = *(const float4*)&Bs[k][colb + 4];
#pragma unroll
                for (int ii = 0; ii < 4; ii++)
#pragma unroll
                    for (int jj = 0; jj < 8; jj++) acc[ii][jj] += a[ii] * b[jj];
            }
            __syncthreads();
        }
    }
#pragma unroll
    for (int ii = 0; ii < 4; ii++) {
        int grow = r0 + rowb + ii;
        if (grow < NNODES) {
#pragma unroll
            for (int jj = 0; jj < 8; jj += 4) {
                float4 o;
                o.x = fmaxf(acc[ii][jj + 0] + bias[colb + jj + 0], 0.f);
                o.y = fmaxf(acc[ii][jj + 1] + bias[colb + jj + 1], 0.f);
                o.z = fmaxf(acc[ii][jj + 2] + bias[colb + jj + 2], 0.f);
                o.w = fmaxf(acc[ii][jj + 3] + bias[colb + jj + 3], 0.f);
                *(float4*)&Y[(size_t)grow * 128 + colb + jj] = o;
            }
        }
    }
}

// ================== tf32 mma.sync final GEMM (sm_80+ path) ===================
__device__ __forceinline__ void mma_tf32(float* c, const uint32_t* a, const uint32_t* b) {
    asm volatile(
        "mma.sync.aligned.m16n8k8.row.col.f32.tf32.tf32.f32 "
        "{%0,%1,%2,%3}, {%4,%5,%6,%7}, {%8,%9}, {%0,%1,%2,%3};\n"
        : "+f"(c[0]), "+f"(c[1]), "+f"(c[2]), "+f"(c[3])
        : "r"(a[0]), "r"(a[1]), "r"(a[2]), "r"(a[3]),
          "r"(b[0]), "r"(b[1]));
}

__device__ __forceinline__ void cp16(uint32_t smem_addr, const void* gptr) {
    asm volatile("cp.async.cg.shared.global [%0], [%1], 16;"
                 :: "r"(smem_addr), "l"(gptr));
}

// ---- pre-shuffle A: weights W[k, i] -> fragment blocks ----------------------
__global__ void shufA_kernel(const float* __restrict__ Wl,
                             const float* __restrict__ Wr) {
    const int tile  = blockIdx.x;          // 0..78  (ib = tile*128)
    const int chunk = blockIdx.y;          // 0..7
    const int phase = chunk >> 2;
    const int kc    = (chunk & 3) * 32;
    const float* __restrict__ W = phase ? Wr : Wl;
    const int ib   = tile * 128;
    const int warp = threadIdx.x >> 5;     // mt = warp
    const int lane = threadIdx.x & 31;     // local k
    const int kt   = lane >> 3;
    const int t4v  = lane & 3;
    const int khi  = (lane >> 2) & 1;
    const float* Wp = W + (size_t)(kc + lane) * NNODES + ib;
    uint32_t* dst = g_Ashuf + (size_t)(tile * 8 + chunk) * 4096;
#pragma unroll
    for (int mm = 0; mm < 16; mm++) {
        const int m = warp * 16 + mm;
        float v = 0.f;
        if (ib + m < NNODES) v = Wp[m];
        const int g  = m & 7;
        const int hi = (m >> 3) & 1;
        const int lw = ((g << 2) | t4v) ^ (kt << 3);
        const int r  = (khi << 1) | hi;
        dst[((kt * 8 + warp) * 32 + lw) * 4 + r] = f2tf32(v);
    }
}

// ---- pre-shuffle B for S1 (chunks 4..7 only) --------------------------------
__global__ void shufB_s1_kernel(const float* __restrict__ S1) {
    const int tile  = blockIdx.x;
    const int chunk = blockIdx.y + 4;      // 4..7
    const int kc    = blockIdx.y * 32;
    const int jb   = tile * 128;
    const int tid  = threadIdx.x;
    const int j    = tid >> 1;
    const int half = tid & 1;
    const int nt   = j >> 3;
    const int g    = j & 7;
    const bool jv  = (jb + j) < NNODES;
    const float* Fp = S1 + (size_t)(jb + j) * FDIM + kc + half * 16;
    uint32_t* dst = g_Bshuf + (size_t)(tile * 8 + chunk) * 4096;
#pragma unroll
    for (int q = 0; q < 4; q++) {
        float4 v4 = make_float4(0.f, 0.f, 0.f, 0.f);
        if (jv) v4 = *(const float4*)(Fp + q * 4);
        float vv[4] = {v4.x, v4.y, v4.z, v4.w};
#pragma unroll
        for (int e = 0; e < 4; e++) {
            const int k  = half * 16 + q * 4 + e;
            const int kt = k >> 3;
            const int kl = k & 7;
            const int lw = ((g << 2) | (kl & 3)) ^ (kt << 3);
            const int r  = kl >> 2;
            dst[((kt * 16 + nt) * 32 + lw) * 2 + r] = f2tf32(vv[e]);
        }
    }
}

// ---- final GEMM: 4 warps, warp tile 64x64, cp.async double-buffered ----------
extern __shared__ uint32_t dynsmem[];   // [2][4096] A + [2][4096] B = 64KB

__global__ void __launch_bounds__(128, 2)
final_tc_kernel(const float* __restrict__ bias,  // [NNODES]
                float* __restrict__ OUT) {       // [NNODES, NNODES]
    uint32_t* sA = dynsmem;           // 2 x 4096
    uint32_t* sB = dynsmem + 8192;    // 2 x 4096

    const int tid  = threadIdx.x;
    const int lane = tid & 31;
    const int warp = tid >> 5;        // 0..3
    const int wm   = warp >> 1;       // 0..1
    const int wn   = warp & 1;        // 0..1
    const int ib   = blockIdx.y * 128;
    const int jb   = blockIdx.x * 128;

    const uint32_t* __restrict__ srcA = g_Ashuf + (size_t)blockIdx.y * 8 * 4096;
    const uint32_t* __restrict__ srcB = g_Bshuf + (size_t)blockIdx.x * 8 * 4096;

    float acc[4][8][4];
#pragma unroll
    for (int mi = 0; mi < 4; mi++)
#pragma unroll
        for (int ni = 0; ni < 8; ni++)
#pragma unroll
            for (int r = 0; r < 4; r++) acc[mi][ni][r] = 0.f;

    const uint32_t sA_u = (uint32_t)__cvta_generic_to_shared(sA);
    const uint32_t sB_u = (uint32_t)__cvta_generic_to_shared(sB);

    auto issue = [&](int chunk) {
        const int buf = chunk & 1;
        const uint32_t* a = srcA + chunk * 4096;
        const uint32_t* b = srcB + chunk * 4096;
        const uint32_t sa = sA_u + buf * 4096 * 4;
        const uint32_t sb = sB_u + buf * 4096 * 4;
#pragma unroll
        for (int it = 0; it < 8; it++) {
            const int off = (tid + it * 128) * 4;     // u32 index, 16B granule
            cp16(sa + off * 4, a + off);
            cp16(sb + off * 4, b + off);
        }
        asm volatile("cp.async.commit_group;");
    };

    issue(0);
    for (int c = 0; c < 8; c++) {
        if (c < 7) {
            issue(c + 1);
            asm volatile("cp.async.wait_group 1;");
        } else {
            asm volatile("cp.async.wait_group 0;");
        }
        __syncthreads();

        const uint32_t* cA = sA + (c & 1) * 4096;
        const uint32_t* cB = sB + (c & 1) * 4096;
#pragma unroll
        for (int kt = 0; kt < 4; kt++) {
            const int lx = lane ^ (kt << 3);
            uint32_t af[4][4];
#pragma unroll
            for (int mi = 0; mi < 4; mi++) {
                const uint4 v = *(const uint4*)&cA[((kt * 8 + wm * 4 + mi) * 32 + lx) * 4];
                af[mi][0] = v.x; af[mi][1] = v.y; af[mi][2] = v.z; af[mi][3] = v.w;
            }
            uint32_t bf[8][2];
#pragma unroll
            for (int ni = 0; ni < 8; ni++) {
                const uint2 v = *(const uint2*)&cB[((kt * 16 + wn * 8 + ni) * 32 + lx) * 2];
                bf[ni][0] = v.x; bf[ni][1] = v.y;
            }
#pragma unroll
            for (int mi = 0; mi < 4; mi++)
#pragma unroll
                for (int ni = 0; ni < 8; ni++)
                    mma_tf32(acc[mi][ni], af[mi], bf[ni]);
        }
        __syncthreads();
    }

    // ---- epilogue: bias + relu + float2 stores -------------------------------
    const int g  = lane >> 2;
    const int t4 = lane & 3;
#pragma unroll
    for (int mi = 0; mi < 4; mi++) {
        const int i0 = ib + (wm * 4 + mi) * 16 + g;
        const int i1 = i0 + 8;
        const float bv0 = (i0 < NNODES) ? bias[i0] : 0.f;
        const float bv1 = (i1 < NNODES) ? bias[i1] : 0.f;
#pragma unroll
        for (int ni = 0; ni < 8; ni++) {
            const int j = jb + (wn * 8 + ni) * 8 + t4 * 2;
            if (j < NNODES) {
                if (i0 < NNODES) {
                    float2 o;
                    o.x = fmaxf(acc[mi][ni][0] + bv0, 0.f);
                    o.y = fmaxf(acc[mi][ni][1] + bv0, 0.f);
                    *(float2*)&OUT[(size_t)i0 * NNODES + j] = o;
                }
                if (i1 < NNODES) {
                    float2 o;
                    o.x = fmaxf(acc[mi][ni][2] + bv1, 0.f);
                    o.y = fmaxf(acc[mi][ni][3] + bv1, 0.f);
                    *(float2*)&OUT[(size_t)i1 * NNODES + j] = o;
                }
            }
        }
    }
}

// ---------------- launch ------------------------------------------------------
extern "C" void kernel_launch(void* const* d_in, const int* in_sizes, int n_in,
                              void* d_out, int out_size) {
    const float* x   = (const float*)d_in[0];
    const int*   ei  = (const int*)d_in[1];
    const int*   src = ei;
    const int*   dst = ei + NEDGES;
    const float *Wl_e1 = (const float*)d_in[2],  *bl_e1 = (const float*)d_in[3],  *Wr_e1 = (const float*)d_in[4];
    const float *Wl_e2 = (const float*)d_in[5],  *bl_e2 = (const float*)d_in[6],  *Wr_e2 = (const float*)d_in[7];
    const float *Wl_a1 = (const float*)d_in[8],  *bl_a1 = (const float*)d_in[9],  *Wr_a1 = (const float*)d_in[10];
    const float *Wl_a2 = (const float*)d_in[11], *bl_a2 = (const float*)d_in[12], *Wr_a2 = (const float*)d_in[13];
    const float *Wl_s1 = (const float*)d_in[14], *bl_s1 = (const float*)d_in[15], *Wr_s1 = (const float*)d_in[16];
    const float *Wl_s2 = (const float*)d_in[17], *bl_s2 = (const float*)d_in[18], *Wr_s2 = (const float*)d_in[19];

    float* out    = (float*)d_out;
    float* xh_out = out + (size_t)NNODES * NNODES;

    float *pB1, *pB2, *pB3, *pAGG, *pAGG2;
    cudaGetSymbolAddress((void**)&pB1,   g_B1);
    cudaGetSymbolAddress((void**)&pB2,   g_B2);
    cudaGetSymbolAddress((void**)&pB3,   g_B3);
    cudaGetSymbolAddress((void**)&pAGG,  g_AGG);
    cudaGetSymbolAddress((void**)&pAGG2, g_AGG2);

    // one-time resources (created on the uncaptured correctness call)
    static cudaStream_t s_a = nullptr;
    static cudaEvent_t ev0 = nullptr, ev_shufA = nullptr, ev_fork = nullptr, ev_join = nullptr;
    if (!s_a) {
        cudaStreamCreateWithFlags(&s_a, cudaStreamNonBlocking);
        cudaEventCreateWithFlags(&ev0,      cudaEventDisableTiming);
        cudaEventCreateWithFlags(&ev_shufA, cudaEventDisableTiming);
        cudaEventCreateWithFlags(&ev_fork,  cudaEventDisableTiming);
        cudaEventCreateWithFlags(&ev_join,  cudaEventDisableTiming);
        cudaFuncSetAttribute(final_tc_kernel,
                             cudaFuncAttributeMaxDynamicSharedMemorySize, 65536);
    }

    const int LG = (NNODES + 63) / 64;                    // 157 blocks
    dim3 fg((NNODES + 127) / 128, (NNODES + 127) / 128);  // 79x79
    dim3 sgA(NTILES, 8);
    dim3 sgB(NTILES, 4);

    // fork side stream at t=0: shufA runs concurrently with CSR build
    cudaEventRecord(ev0, 0);
    cudaStreamWaitEvent(s_a, ev0, 0);
    shufA_kernel<<<sgA, 256, 0, s_a>>>(Wl_s2, Wr_s2);
    cudaEventRecord(ev_shufA, s_a);

    // CSR build (main)
    zero_kernel<<<(NNODES + 255) / 256, 256>>>();
    count_kernel<<<(NEDGES + 255) / 256, 256>>>(dst);
    scan_kernel<<<1, 1024>>>();
    fill_kernel<<<(NEDGES + 255) / 256, 256>>>(src, dst);

    // encoder (shared prefix)
    agg_kernel<<<AGG_GRID, 256>>>(x, pAGG);
    layer_kernel<<<LG, 256>>>(pAGG, x, Wl_e1, Wr_e1, bl_e1, pB1);       // h1
    agg_kernel<<<AGG_GRID, 256>>>(pB1, pAGG);
    layer_kernel<<<LG, 256>>>(pAGG, pB1, Wl_e2, Wr_e2, bl_e2, pB2);     // h2

    // fork: attribute decoder on side stream (independent of s-branch)
    cudaEventRecord(ev_fork, 0);
    cudaStreamWaitEvent(s_a, ev_fork, 0);
    agg_kernel<<<AGG_GRID, 256, 0, s_a>>>(pB2, pAGG2);
    layer_kernel<<<LG, 256, 0, s_a>>>(pAGG2, pB2, Wl_a1, Wr_a1, bl_a1, pB3);   // a1
    agg_kernel<<<AGG_GRID, 256, 0, s_a>>>(pB3, pAGG2);
    layer_kernel<<<LG, 256, 0, s_a>>>(pAGG2, pB3, Wl_a2, Wr_a2, bl_a2, xh_out);// xh
    cudaEventRecord(ev_join, s_a);

    // structure decoder + final GEMM on main stream
    agg_kernel<<<AGG_GRID, 256>>>(pB2, pAGG);
    layer_kernel<<<LG, 256>>>(pAGG, pB2, Wl_s1, Wr_s1, bl_s1, pB1);     // s1
    shufB_s1_kernel<<<sgB, 256>>>(pB1);                                 // B chunks 4-7
    agg_shuf_kernel<<<AGG_GRID, 256>>>(pB1);                            // B chunks 0-3 (fused agg)
    cudaStreamWaitEvent(0, ev_shufA, 0);
    final_tc_kernel<<<fg, 128, 65536>>>(bl_s2, out);                    // s

    // join a-branch before capture ends
    cudaStreamWaitEvent(0, ev_join, 0);
}